// round 17
// baseline (speedup 1.0000x reference)
#include <cuda_runtime.h>
#include <cstdint>

// Detail loss, simplified:
//   D = sum_c (infer - ref)   per image plane
//   out = (sum|D[w+1]-D[w-1]| + sum|D[h+1]-D[h-1]|) * 0.25 / (98*258*256)
// TMA-bulk pipeline: block owns a 32-row strip (window 34 rows = 17 stages of
// 2 rows). Raw data streams via cp.async.bulk (6 planes x 2KB per stage) into
// a 3-slot smem ring with mbarrier complete_tx. 128 threads convert each stage
// to D rows in smem, then stencil the rows one stage behind. The TMA engine
// holds the in-flight bytes (no registers, no warp scoreboard) with 2KB
// contiguous bursts -> probes whether the 5.3TB/s LDG plateau is request-path.

#define NIMG   98
#define IMG_H  256
#define IMG_W  256
#define SROWS  32
#define STRIPS (IMG_H / SROWS)           // 8
#define NBLOCKS (NIMG * STRIPS)          // 784
#define PLANE  (IMG_H * IMG_W)
#define WROWS  34                        // window rows (strip + 2 halo)
#define NSTAGE 17                        // 2 rows per stage
#define RING   3
#define ROW_B  (IMG_W * 4)               // 1024 bytes per plane-row
#define PST_B  (2 * ROW_B)               // 2048 per plane per stage
#define STAGE_B (6 * PST_B)              // 12288
#define D_BYTES (WROWS * ROW_B)          // 34816
#define RING_OFF_B  D_BYTES
#define MBAR_OFF_B  (RING_OFF_B + RING * STAGE_B)   // 71680
#define SMEM_TOTAL  (MBAR_OFF_B + RING * 8 + 8)     // 71712

__device__ float        g_partials[NBLOCKS];
__device__ unsigned int g_count;     // zero-init; reset each launch by last block

#define BULK_G2S(dst, src, bytes, mbar)                                        \
    asm volatile("cp.async.bulk.shared::cluster.global.mbarrier::complete_tx::bytes " \
                 "[%0], [%1], %2, [%3];"                                       \
                 :: "r"(dst), "l"(src), "r"(bytes), "r"(mbar) : "memory")

#define MBAR_INIT(mbar, cnt)                                                   \
    asm volatile("mbarrier.init.shared.b64 [%0], %1;" :: "r"(mbar), "r"(cnt) : "memory")

#define MBAR_EXPECT_TX(mbar, bytes)                                            \
    asm volatile("mbarrier.arrive.expect_tx.shared.b64 _, [%0], %1;"           \
                 :: "r"(mbar), "r"(bytes) : "memory")

__device__ __forceinline__ void mbar_wait(uint32_t mbar, uint32_t parity) {
    asm volatile(
        "{\n\t"
        ".reg .pred P;\n\t"
        "WAIT_%=:\n\t"
        "mbarrier.try_wait.parity.acquire.cta.shared::cta.b64 P, [%0], %1, 0x989680;\n\t"
        "@P bra.uni DONE_%=;\n\t"
        "bra.uni WAIT_%=;\n\t"
        "DONE_%=:\n\t"
        "}" :: "r"(mbar), "r"(parity) : "memory");
}

__global__ void __launch_bounds__(128)
detail_kernel(const float* __restrict__ infer, const float* __restrict__ ref,
              float* __restrict__ out) {
    extern __shared__ float smem[];
    const uint32_t sbase = (uint32_t)__cvta_generic_to_shared(smem);
    float* Dbuf = smem;                              // WROWS x 256 floats
    float* ringf = smem + RING_OFF_B / 4;
    const uint32_t mbar0 = sbase + MBAR_OFF_B;

    const int tid = threadIdx.x;
    const int blk = blockIdx.x;
    const int n     = blk / STRIPS;
    const int strip = blk % STRIPS;
    const int r0    = strip * SROWS;

    // Plane base pointers: 0-2 infer channels, 3-5 ref channels.
    const float* pb[6];
    {
        const float* pi = infer + (size_t)n * 3 * PLANE;
        const float* pr = ref   + (size_t)n * 3 * PLANE;
        pb[0] = pi; pb[1] = pi + PLANE; pb[2] = pi + 2 * PLANE;
        pb[3] = pr; pb[4] = pr + PLANE; pb[5] = pr + 2 * PLANE;
    }

    if (tid == 0) {
        #pragma unroll
        for (int k = 0; k < RING; k++) MBAR_INIT(mbar0 + k * 8, 1);
    }
    __syncthreads();

    // Issue one stage's TMA: window rows w=2s,2s+1 <-> global rows r0-1+w.
    auto issue = [&](int s) {
        const int g0 = r0 - 1 + 2 * s;
        const bool v0 = (unsigned)g0 < IMG_H;
        const bool v1 = (unsigned)(g0 + 1) < IMG_H;
        const int nv = (int)v0 + (int)v1;
        const uint32_t mb   = mbar0 + (s % RING) * 8;
        const uint32_t slot = sbase + RING_OFF_B + (s % RING) * STAGE_B;
        MBAR_EXPECT_TX(mb, nv * 6 * ROW_B);
        const int gs = v0 ? g0 : g0 + 1;             // first valid row
        const uint32_t doff = v0 ? 0u : (uint32_t)ROW_B;
        const uint32_t sz = (uint32_t)(nv * ROW_B);
        #pragma unroll
        for (int p = 0; p < 6; p++)
            BULK_G2S(slot + p * PST_B + doff, pb[p] + (size_t)gs * IMG_W, sz, mb);
    };

    if (tid == 0) { issue(0); issue(1); issue(2); }

    const int rl = tid >> 6;          // 0/1: row within stage
    const int c4 = (tid & 63) * 4;    // 4 columns per thread

    float sum = 0.f;

    for (int s = 0; s < NSTAGE; s++) {
        mbar_wait(mbar0 + (s % RING) * 8, (unsigned)(s / RING) & 1u);

        // Convert: window row w = 2s+rl (global r0-1+w) -> D row in smem.
        {
            const int w = 2 * s + rl;
            const int g = r0 - 1 + w;
            float4 d = make_float4(0.f, 0.f, 0.f, 0.f);
            if ((unsigned)g < IMG_H) {
                const float* sp = ringf + (s % RING) * (STAGE_B / 4)
                                + rl * IMG_W + c4;
                const float4 a0 = *(const float4*)(sp);
                const float4 a1 = *(const float4*)(sp + 512);
                const float4 a2 = *(const float4*)(sp + 1024);
                const float4 b0 = *(const float4*)(sp + 1536);
                const float4 b1 = *(const float4*)(sp + 2048);
                const float4 b2 = *(const float4*)(sp + 2560);
                d.x = (a0.x - b0.x) + (a1.x - b1.x) + (a2.x - b2.x);
                d.y = (a0.y - b0.y) + (a1.y - b1.y) + (a2.y - b2.y);
                d.z = (a0.z - b0.z) + (a1.z - b1.z) + (a2.z - b2.z);
                d.w = (a0.w - b0.w) + (a1.w - b1.w) + (a2.w - b2.w);
            }
            *(float4*)(Dbuf + w * IMG_W + c4) = d;
        }
        __syncthreads();   // conversion done: slot free, new D rows visible

        if (tid == 0 && s + RING < NSTAGE) issue(s + RING);

        // Stencil rows w = 2s-1+rl (valid interior: 1..SROWS). Needs D rows
        // up to 2s+1 (just written). Overlaps the newly issued TMA.
        {
            const int w = 2 * s - 1 + rl;
            if (w >= 1 && w <= SROWS) {
                const float* Dw = Dbuf + w * IMG_W;
                const float4 ctr = *(const float4*)(Dw + c4);
                const float  l = (c4 == 0) ? 0.f : Dw[c4 - 1];
                const float  r = (c4 + 4 >= IMG_W) ? 0.f : Dw[c4 + 4];
                const float4 up = *(const float4*)(Dw - IMG_W + c4);
                const float4 dn = *(const float4*)(Dw + IMG_W + c4);
                sum += fabsf(ctr.y - l) + fabsf(ctr.z - ctr.x)
                     + fabsf(ctr.w - ctr.y) + fabsf(r - ctr.z);
                sum += fabsf(dn.x - up.x) + fabsf(dn.y - up.y)
                     + fabsf(dn.z - up.z) + fabsf(dn.w - up.w);
            }
        }
    }

    // Block reduction (4 warps).
    #pragma unroll
    for (int off = 16; off > 0; off >>= 1)
        sum += __shfl_down_sync(0xffffffffu, sum, off);
    __shared__ float wsum[4];
    __shared__ bool  is_last;
    if ((tid & 31) == 0) wsum[tid >> 5] = sum;
    __syncthreads();
    if (tid == 0) {
        float s4 = wsum[0] + wsum[1] + wsum[2] + wsum[3];
        g_partials[blk] = s4;
        __threadfence();
        is_last = (atomicAdd(&g_count, 1u) == NBLOCKS - 1);
    }
    __syncthreads();

    if (is_last) {
        float t = 0.f;
        for (int i = tid; i < NBLOCKS; i += 128)
            t += __ldcg(&g_partials[i]);
        #pragma unroll
        for (int off = 16; off > 0; off >>= 1)
            t += __shfl_down_sync(0xffffffffu, t, off);
        if ((tid & 31) == 0) wsum[tid >> 5] = t;
        __syncthreads();
        if (tid == 0) {
            float u = wsum[0] + wsum[1] + wsum[2] + wsum[3];
            // 0.5 (gradient coeff) * 0.5 (avg of two losses) / (98*258*256)
            out[0] = u * (0.25f / 6472704.0f);
            g_count = 0;   // deterministic across graph replays
        }
    }
}

extern "C" void kernel_launch(void* const* d_in, const int* in_sizes, int n_in,
                              void* d_out, int out_size) {
    const float* infer = (const float*)d_in[0];
    const float* ref   = (const float*)d_in[1];
    cudaFuncSetAttribute(detail_kernel,
                         cudaFuncAttributeMaxDynamicSharedMemorySize, SMEM_TOTAL);
    detail_kernel<<<NBLOCKS, 128, SMEM_TOTAL>>>(infer, ref, (float*)d_out);
}